// round 9
// baseline (speedup 1.0000x reference)
#include <cuda_runtime.h>
#include <cstdint>

#define NA     17064
#define KTOP   1000
#define NBINS  16384
#define CCAP   4096
#define NT     1024
#define B      16
#define NCTA   128          // 8 CTAs per batch, co-resident (1 CTA/SM)
#define FULL   0xffffffffu

typedef unsigned long long u64;

// ---------------- static device scratch ----------------
__device__ unsigned ghist[B][NBINS];      // zero-init; re-zeroed each pass
__device__ unsigned gcnt[B];
__device__ u64      gkey[B][CCAP];
__device__ float    gssc[B][KTOP];
__device__ unsigned gslab[B][KTOP];
__device__ unsigned gvbits[B][32];
__device__ float4   gsbox[B][KTOP];
__device__ float    gsx1[B][KTOP], gsy1[B][KTOP], gsx2[B][KTOP],
                    gsy2[B][KTOP], gsar[B][KTOP];
__device__ __align__(16) unsigned gmat[B][KTOP][32];
__device__ unsigned gdiag[B][1024];
__device__ unsigned gprog[B][8];          // per-producer wave progress
__device__ unsigned gbarc[B][4];          // per-batch epoch barrier counters

// Exact sigmoid: float exp via double exp (correctly rounded to float =>
// matches faithful libm expf), then float add + div as XLA expands logistic.
__device__ __forceinline__ float sigx(float x) {
    float t = (float)exp(-(double)x);
    return __fdiv_rn(1.0f, __fadd_rn(1.0f, t));
}
// Fast approximate sigmoid — superset selection only.
__device__ __forceinline__ float siga(float x) {
    return __fdividef(1.0f, 1.0f + __expf(-x));
}
__device__ __forceinline__ u64 cex_shfl(u64 v, int j, bool up, int lane) {
    u64 p = __shfl_xor_sync(FULL, v, j);
    bool lower = ((lane & j) == 0);
    return (lower == up) ? (v > p ? v : p) : (v < p ? v : p);
}
// per-batch barrier (8 CTAs), epoch-based, graph-replay safe
__device__ __forceinline__ void bbarrier(int b, int k) {
    __syncthreads();
    if (threadIdx.x == 0) {
        __threadfence();
        unsigned old   = atomicAdd(&gbarc[b][k], 1u);
        unsigned epoch = old >> 3;
        volatile unsigned* p = &gbarc[b][k];
        unsigned target = (epoch + 1u) << 3;
        while (*p < target) { }
        __threadfence();
    }
    __syncthreads();
}
// guarded warp suffix-sum (inclusive from high lanes): s_l = sum_{q>=l} v_q
__device__ __forceinline__ unsigned suffix_sum(unsigned v, int lane) {
#pragma unroll
    for (int o = 1; o < 32; o <<= 1) {
        unsigned t = __shfl_down_sync(FULL, v, o);
        if (lane + o < 32) v += t;
    }
    return v;
}

#define SMEM_TOTAL 132096   // max(32KB sort, 20KB boxes, 125KB smat + 4KB sdiag)
extern __shared__ unsigned char smem_raw[];

__global__ void __launch_bounds__(NT, 1)
fcos_persist(const float* __restrict__ cls, const float* __restrict__ ctr,
             const float* __restrict__ reg, const float* __restrict__ coords,
             const float* __restrict__ pstr, float* __restrict__ out)
{
    const int cta  = blockIdx.x;
    const int b    = cta >> 3;
    const int r    = cta & 7;
    const int tid  = threadIdx.x;
    const int lane = tid & 31;
    const int wid  = tid >> 5;

    __shared__ unsigned chunk[1024];
    __shared__ unsigned supr[32];
    __shared__ float redmax[32], redmin[32];
    __shared__ float s_mx, s_mn;
    __shared__ unsigned s_thr, srem[32];
    __shared__ volatile unsigned scopied;

    const float4* clsB = (const float4*)cls + (size_t)b * NA;
    const float*  ctrB = ctr + (size_t)b * NA;

    // ============ Phase 1: histogram only (8 CTAs/batch) ====================
    if (r == 0 && tid == 0) gcnt[b] = 0;
    for (int i = r * NT + tid; i < NA; i += 8 * NT) {
        float4 c = clsB[i];
        float m = fmaxf(fmaxf(c.x, c.y), fmaxf(c.z, c.w));
        float score = __fsqrt_rn(siga(m) * siga(ctrB[i]));
        atomicAdd(&ghist[b][__float_as_uint(score) >> 16], 1u);
    }
    bbarrier(b, 0);

    // ============ Phase 2: threshold (warp-parallel suffix scans) ===========
    { unsigned s = 0; int base = tid * 16;
#pragma unroll
      for (int q = 0; q < 16; ++q) s += ghist[b][base + q];
      chunk[tid] = s; }
    __syncthreads();
    { unsigned s = chunk[wid * 32 + lane];
#pragma unroll
      for (int o = 16; o; o >>= 1) s += __shfl_xor_sync(FULL, s, o);
      if (lane == 0) supr[wid] = s; }
    __syncthreads();
    if (wid == 0) {
        unsigned suf = suffix_sum(supr[lane], lane);
        unsigned m1  = __ballot_sync(FULL, suf >= KTOP);
        int sblk     = 31 - __clz(m1);
        unsigned above = (sblk < 31) ? __shfl_sync(FULL, suf, sblk + 1) : 0u;
        unsigned cs  = suffix_sum(chunk[sblk * 32 + lane], lane);
        unsigned m2  = __ballot_sync(FULL, cs + above >= KTOP);
        int cc       = 31 - __clz(m2);
        unsigned above2 = above + ((cc < 31) ? __shfl_sync(FULL, cs, cc + 1) : 0u);
        int binbase  = (sblk * 32 + cc) * 16;
        unsigned bs  = suffix_sum((lane < 16) ? ghist[b][binbase + lane] : 0u, lane);
        unsigned m3  = __ballot_sync(FULL, bs + above2 >= KTOP);
        int bb       = 31 - __clz(m3);
        if (lane == 0) {
            int T = binbase + bb;
            s_thr = (T > 0) ? (unsigned)(T - 1) : 0u;   // one-bin superset margin
        }
    }
    __syncthreads();
    const unsigned T = s_thr;

    // ============ Phase 2b: fused compact + exact rescore ===================
    for (int i = r * NT + tid; i < NA; i += 8 * NT) {
        float4 c = clsB[i];
        float xs0 = c.x, xs1 = c.y, xs2 = c.z, xs3 = c.w;
        float m = fmaxf(fmaxf(xs0, xs1), fmaxf(xs2, xs3));
        float ctrv = ctrB[i];
        float sa = __fsqrt_rn(siga(m) * siga(ctrv));
        if ((__float_as_uint(sa) >> 16) >= T) {
            unsigned p = atomicAdd(&gcnt[b], 1u);
            if (p < CCAP) {
                int im = 0; float mm = xs0;
                if (xs1 > mm) { mm = xs1; im = 1; }
                if (xs2 > mm) { mm = xs2; im = 2; }
                if (xs3 > mm) { mm = xs3; im = 3; }
                float sm = sigx(mm);                    // == max of the 4 sigmoids
                int lab = im;
                if (im > 0) {                           // first-argmax tie guard
                    float lim = mm - 1e-4f;
                    if (xs0 > lim || (im > 1 && xs1 > lim) || (im > 2 && xs2 > lim)) {
                        if (xs0 > lim && sigx(xs0) == sm) lab = 0;
                        else if (im > 1 && xs1 > lim && sigx(xs1) == sm) lab = 1;
                        else if (im > 2 && xs2 > lim && sigx(xs2) == sm) lab = 2;
                    }
                }
                float sctr  = sigx(ctrv);
                float score = __fsqrt_rn(__fmul_rn(sm, sctr));
                gkey[b][p] = ((u64)__float_as_uint(score) << 32)
                           | ((u64)(0x7FFFu - (unsigned)i) << 4) | (u64)(lab + 1);
            }
        }
    }
    bbarrier(b, 1);

    int C = (int)gcnt[b]; if (C > CCAP) C = CCAP;

    // ============ Phase 3: r==0 sorts + builds boxes; r>0 zero hist =========
    if (r == 0) {
        u64* cand = (u64*)smem_raw;
        if (C <= 2048) {
            const int base = wid * 64;
            u64 r0 = (base + lane      < C) ? gkey[b][base + lane]      : 0ULL;
            u64 r1 = (base + 32 + lane < C) ? gkey[b][base + 32 + lane] : 0ULL;
#pragma unroll
            for (int k2 = 2; k2 <= 16; k2 <<= 1) {
                bool up = ((lane & k2) == 0);
#pragma unroll
                for (int j = k2 >> 1; j > 0; j >>= 1) {
                    r0 = cex_shfl(r0, j, up, lane);
                    r1 = cex_shfl(r1, j, up, lane);
                }
            }
#pragma unroll
            for (int j = 16; j > 0; j >>= 1) {
                r0 = cex_shfl(r0, j, true,  lane);
                r1 = cex_shfl(r1, j, false, lane);
            }
            {
                bool up = ((base & 64) == 0);
                u64 lo = r0, hi = r1;
                if (up) { r0 = lo > hi ? lo : hi; r1 = lo > hi ? hi : lo; }
                else    { r0 = lo < hi ? lo : hi; r1 = lo < hi ? hi : lo; }
#pragma unroll
                for (int j = 16; j > 0; j >>= 1) {
                    r0 = cex_shfl(r0, j, up, lane);
                    r1 = cex_shfl(r1, j, up, lane);
                }
            }
            for (int k2 = 128; k2 <= 2048; k2 <<= 1) {
                cand[base + lane] = r0; cand[base + 32 + lane] = r1;
                __syncthreads();
                for (int j = k2 >> 1; j >= 64; j >>= 1) {
                    for (int t = tid; t < 2048; t += NT) {
                        int ixj = t ^ j;
                        if (ixj > t) {
                            u64 a = cand[t], b2 = cand[ixj];
                            bool up = ((t & k2) == 0);
                            if (up ? (a < b2) : (a > b2)) { cand[t] = b2; cand[ixj] = a; }
                        }
                    }
                    __syncthreads();
                }
                r0 = cand[base + lane]; r1 = cand[base + 32 + lane];
                bool up = ((base & k2) == 0);
                u64 lo = r0, hi = r1;
                if (up) { r0 = lo > hi ? lo : hi; r1 = lo > hi ? hi : lo; }
                else    { r0 = lo < hi ? lo : hi; r1 = lo < hi ? hi : lo; }
#pragma unroll
                for (int j = 16; j > 0; j >>= 1) {
                    r0 = cex_shfl(r0, j, up, lane);
                    r1 = cex_shfl(r1, j, up, lane);
                }
            }
            cand[base + lane] = r0; cand[base + 32 + lane] = r1;
            __syncthreads();
        } else {
            for (int i = tid; i < CCAP; i += NT)
                cand[i] = (i < C) ? gkey[b][i] : 0ULL;
            __syncthreads();
            for (int k2 = 2; k2 <= CCAP; k2 <<= 1)
                for (int j = k2 >> 1; j > 0; j >>= 1) {
                    for (int t = tid; t < CCAP; t += NT) {
                        int ixj = t ^ j;
                        if (ixj > t) {
                            u64 a = cand[t], b2 = cand[ixj];
                            bool up = ((t & k2) == 0);
                            if (up ? (a < b2) : (a > b2)) { cand[t] = b2; cand[ixj] = a; }
                        }
                    }
                    __syncthreads();
                }
        }

        float x1 = 0, y1 = 0, x2 = 0, y2 = 0, score = 0;
        int label = 0; bool validf = false;
        if (tid < KTOP) {
            u64 key = cand[tid];
            score  = __uint_as_float((unsigned)(key >> 32));
            label  = (int)(key & 0xFull);
            int idx = 0x7FFF - (int)((key >> 4) & 0x7FFFull);
            validf = (score >= 0.05f);

            float4 r4 = ((const float4*)reg)[(size_t)b * NA + idx];
            float2 xy = ((const float2*)coords)[idx];
            float  st = pstr[idx];
            x1 = __fsub_rn(xy.x, __fmul_rn(r4.x, st));
            y1 = __fsub_rn(xy.y, __fmul_rn(r4.y, st));
            x2 = __fadd_rn(xy.x, __fmul_rn(r4.z, st));
            y2 = __fadd_rn(xy.y, __fmul_rn(r4.w, st));
            x1 = fminf(fmaxf(x1, 0.0f), 1023.0f);
            y1 = fminf(fmaxf(y1, 0.0f), 799.0f);
            x2 = fminf(fmaxf(x2, 0.0f), 1023.0f);
            y2 = fminf(fmaxf(y2, 0.0f), 799.0f);

            gsbox[b][tid] = make_float4(x1, y1, x2, y2);
            gssc[b][tid]  = score;
            gslab[b][tid] = (unsigned)label;
        }
        { unsigned vb = __ballot_sync(FULL, validf);
          if (lane == 0) gvbits[b][wid] = vb; }

        float vmax = -1000000000.0f, vmin = 1000000000.0f;
        if (tid < KTOP && validf) {
            vmax = fmaxf(fmaxf(x1, y1), fmaxf(x2, y2));
            vmin = fminf(fminf(x1, y1), fminf(x2, y2));
        }
#pragma unroll
        for (int o = 16; o; o >>= 1) {
            vmax = fmaxf(vmax, __shfl_xor_sync(FULL, vmax, o));
            vmin = fminf(vmin, __shfl_xor_sync(FULL, vmin, o));
        }
        if (lane == 0) { redmax[wid] = vmax; redmin[wid] = vmin; }
        __syncthreads();
        if (tid == 0) {
            float mx = redmax[0], mn = redmin[0];
            for (int w = 1; w < 32; ++w) { mx = fmaxf(mx, redmax[w]); mn = fminf(mn, redmin[w]); }
            s_mx = mx; s_mn = mn;
        }
        __syncthreads();
        if (tid < KTOP) {
            float off = __fmul_rn((float)label, __fadd_rn(__fsub_rn(s_mx, s_mn), 1.0f));
            float a  = __fadd_rn(x1, off), bb = __fadd_rn(y1, off);
            float cc = __fadd_rn(x2, off), dd = __fadd_rn(y2, off);
            gsx1[b][tid] = a;  gsy1[b][tid] = bb;
            gsx2[b][tid] = cc; gsy2[b][tid] = dd;
            gsar[b][tid] = __fmul_rn(__fsub_rn(cc, a), __fsub_rn(dd, bb));
        }
    } else {
        int z0 = (r - 1) * 2341, z1 = (r == 7) ? NBINS : z0 + 2341;
        for (int i = z0 + tid; i < z1; i += NT) ghist[b][i] = 0;
        if (tid == 0) *((volatile unsigned*)&gprog[b][r]) = 0u;  // wave reset
    }
    bbarrier(b, 2);

    // ============ Phase 4: producers r=1..7 — matrix rows in 5 waves ========
    if (r > 0) {
        float* sx1 = (float*)smem_raw;
        float* sy1 = sx1 + KTOP; float* sx2 = sy1 + KTOP;
        float* sy2 = sx2 + KTOP; float* sar = sy2 + KTOP;
        for (int j = tid; j < KTOP; j += NT) {
            sx1[j] = gsx1[b][j]; sy1[j] = gsy1[b][j];
            sx2[j] = gsx2[b][j]; sy2[j] = gsy2[b][j];
            sar[j] = gsar[b][j];
        }
        __syncthreads();

        for (int t = 0; t < 5; ++t) {
            int k = 32 * t + wid;
            if (k < 143) {
                int i = 7 * k + (r - 1);
                if (i < KTOP) {
                    float ax1 = sx1[i], ay1 = sy1[i], ax2 = sx2[i], ay2 = sy2[i], aa = sar[i];
                    unsigned myword = 0;
                    int jc0 = (i + 1) >> 5;
                    for (int jc = jc0; jc < 32; ++jc) {
                        int j = jc * 32 + lane;
                        bool sup = false;
                        if (j > i && j < KTOP) {
                            float ix1 = fmaxf(ax1, sx1[j]);
                            float iy1 = fmaxf(ay1, sy1[j]);
                            float ix2 = fminf(ax2, sx2[j]);
                            float iy2 = fminf(ay2, sy2[j]);
                            float iw  = fmaxf(__fsub_rn(ix2, ix1), 0.0f);
                            float ih  = fmaxf(__fsub_rn(iy2, iy1), 0.0f);
                            float inter = __fmul_rn(iw, ih);
                            float uni = fmaxf(__fsub_rn(__fadd_rn(aa, sar[j]), inter), 1e-9f);
                            sup = __fdiv_rn(inter, uni) > 0.5f;
                        }
                        unsigned wbits = __ballot_sync(FULL, sup);
                        if (lane == jc) myword = wbits;
                    }
                    gmat[b][i][lane] = myword;
                    if (lane == (i >> 5)) gdiag[b][i] = myword;
                }
            }
            __syncthreads();
            if (tid == 0) {
                __threadfence();
                *((volatile unsigned*)&gprog[b][r]) = (unsigned)(t + 1);
            }
        }
        return;
    }

    // ============ Phase 5: CTA0 — pipelined copy (warps 1-31) + NMS (warp 0)
    {
        unsigned* smat  = (unsigned*)smem_raw;              // [1000][32]
        unsigned* sdiag = (unsigned*)(smem_raw + 128000);   // [1024]
        if (tid >= KTOP) sdiag[tid] = 0u;
        if (tid == 0) scopied = 0u;
        __syncthreads();

        if (wid > 0) {
            int copIdx = tid - 32;                          // 0..991
            for (int t = 0; t < 5; ++t) {
                if (wid == 1) {
                    bool ok;
                    do {
                        unsigned v = (lane < 7) ?
                            *((volatile unsigned*)&gprog[b][1 + lane]) : FULL;
                        ok = __all_sync(FULL, v >= (unsigned)(t + 1));
                    } while (!ok);
                    __threadfence();
                }
                asm volatile("bar.sync 1, 992;" ::: "memory");
                int rowbase = 224 * t;
                int rowend  = (224 * (t + 1) < KTOP) ? 224 * (t + 1) : KTOP;
                int nrow    = rowend - rowbase;
                const uint4* src = (const uint4*)&gmat[b][rowbase][0];
                uint4* dst = (uint4*)&smat[rowbase * 32];
                for (int u = copIdx; u < nrow * 8; u += 992) dst[u] = src[u];
                for (int d = copIdx; d < nrow; d += 992)
                    sdiag[rowbase + d] = gdiag[b][rowbase + d];
                asm volatile("bar.sync 1, 992;" ::: "memory");
                if (wid == 1 && lane == 0) {
                    __threadfence_block();
                    scopied = (unsigned)(t + 1);
                }
            }
        } else {
            unsigned removed = ~gvbits[b][lane];            // lane owns [32l, 32l+32)
            for (int bk = 0; bk < 32; ++bk) {
                unsigned needT = (unsigned)((32 * (bk + 1) + 223) / 224);
                while (scopied < needT) { }
                __threadfence_block();
                unsigned curw = __shfl_sync(FULL, removed, bk);
                unsigned kept = 0;
                if (lane == 0) {
                    const uint4* dg = (const uint4*)(sdiag + bk * 32);
                    unsigned rem = curw;
#pragma unroll
                    for (int q = 0; q < 8; ++q) {
                        uint4 v = dg[q];
                        int j0 = q * 4;
                        if (!((rem >> (j0 + 0)) & 1u)) { kept |= 1u << (j0 + 0); rem |= v.x; }
                        if (!((rem >> (j0 + 1)) & 1u)) { kept |= 1u << (j0 + 1); rem |= v.y; }
                        if (!((rem >> (j0 + 2)) & 1u)) { kept |= 1u << (j0 + 2); rem |= v.z; }
                        if (!((rem >> (j0 + 3)) & 1u)) { kept |= 1u << (j0 + 3); rem |= v.w; }
                    }
                }
                kept = __shfl_sync(FULL, kept, 0);
#pragma unroll 4
                for (int jj = 0; jj < 32; ++jj) {
                    if ((kept >> jj) & 1u)
                        removed |= smat[(bk * 32 + jj) * 32 + lane];
                }
            }
            srem[lane] = removed;
        }
        __syncthreads();

        if (tid < KTOP) {
            bool k = ((srem[tid >> 5] >> (tid & 31)) & 1u) == 0u;
            float so = k ? gssc[b][tid] : 0.0f;
            float lo = k ? (float)gslab[b][tid] : 0.0f;
            float4 bx = gsbox[b][tid];
            if (!k) bx = make_float4(0.f, 0.f, 0.f, 0.f);
            out[(size_t)b * KTOP + tid] = so;
            out[(size_t)(B * KTOP) + (size_t)b * KTOP + tid] = lo;
            size_t base = (size_t)(2 * B * KTOP) + ((size_t)b * KTOP + tid) * 4;
            out[base + 0] = bx.x; out[base + 1] = bx.y;
            out[base + 2] = bx.z; out[base + 3] = bx.w;
        }
    }
}

extern "C" void kernel_launch(void* const* d_in, const int* in_sizes, int n_in,
                              void* d_out, int out_size) {
    (void)in_sizes; (void)n_in; (void)out_size;
    static bool attr_done = false;
    if (!attr_done) {
        cudaFuncSetAttribute(fcos_persist, cudaFuncAttributeMaxDynamicSharedMemorySize,
                             SMEM_TOTAL);
        attr_done = true;
    }
    fcos_persist<<<NCTA, NT, SMEM_TOTAL>>>(
        (const float*)d_in[0], (const float*)d_in[1], (const float*)d_in[2],
        (const float*)d_in[3], (const float*)d_in[4], (float*)d_out);
}

// round 10
// speedup vs baseline: 1.0121x; 1.0121x over previous
#include <cuda_runtime.h>
#include <cstdint>

#define NA     17064
#define KTOP   1000
#define NBINS  16384
#define CCAP   4096
#define NT     1024
#define B      16
#define NCTA   128
#define FULL   0xffffffffu

typedef unsigned long long u64;

// ---------------- static device scratch ----------------
__device__ unsigned ghist[B][NBINS];      // zero-init; re-zeroed each pass
__device__ unsigned gcnt[B];
__device__ u64      gkey[B][CCAP];
__device__ unsigned grank[B][CCAP];       // zeroed in P1 each pass
__device__ float    gssc[B][KTOP];
__device__ unsigned gslab[B][KTOP];
__device__ unsigned gvbits[B][32];
__device__ float4   gsbox[B][KTOP];
__device__ float    gsx1[B][KTOP], gsy1[B][KTOP], gsx2[B][KTOP],
                    gsy2[B][KTOP], gsar[B][KTOP];
__device__ __align__(16) unsigned gmat[B][KTOP][32];
__device__ __align__(16) unsigned gdiag[B][1024];
__device__ unsigned gnzw[B][32];          // row-nonzero bitmap, zeroed each pass
__device__ unsigned gbarc[B][8];          // per-batch epoch barrier counters

// Exact sigmoid: float exp via double exp (correctly rounded to float =>
// matches faithful libm expf), then float add + div as XLA expands logistic.
__device__ __forceinline__ float sigx(float x) {
    float t = (float)exp(-(double)x);
    return __fdiv_rn(1.0f, __fadd_rn(1.0f, t));
}
// Fast approximate sigmoid — superset selection only.
__device__ __forceinline__ float siga(float x) {
    return __fdividef(1.0f, 1.0f + __expf(-x));
}
// per-batch barrier (8 CTAs), epoch-based, graph-replay safe
__device__ __forceinline__ void bbarrier(int b, int k) {
    __syncthreads();
    if (threadIdx.x == 0) {
        __threadfence();
        unsigned old   = atomicAdd(&gbarc[b][k], 1u);
        unsigned epoch = old >> 3;
        volatile unsigned* p = &gbarc[b][k];
        unsigned target = (epoch + 1u) << 3;
        while (*p < target) { }
        __threadfence();
    }
    __syncthreads();
}
// guarded warp suffix-sum (inclusive from high lanes)
__device__ __forceinline__ unsigned suffix_sum(unsigned v, int lane) {
#pragma unroll
    for (int o = 1; o < 32; o <<= 1) {
        unsigned t = __shfl_down_sync(FULL, v, o);
        if (lane + o < 32) v += t;
    }
    return v;
}

#define SMEM_TOTAL 33024    // max: rank keys 32KB; boxes 20KB; sdiag 4KB
extern __shared__ unsigned char smem_raw[];

__global__ void __launch_bounds__(NT, 1)
fcos_persist(const float* __restrict__ cls, const float* __restrict__ ctr,
             const float* __restrict__ reg, const float* __restrict__ coords,
             const float* __restrict__ pstr, float* __restrict__ out)
{
    const int cta  = blockIdx.x;
    const int b    = cta >> 3;
    const int r    = cta & 7;
    const int tid  = threadIdx.x;
    const int lane = tid & 31;
    const int wid  = tid >> 5;

    __shared__ unsigned chunk[1024];
    __shared__ unsigned supr[32];
    __shared__ float redmax[32], redmin[32];
    __shared__ float s_mx, s_mn;
    __shared__ unsigned s_thr, srem[32];

    const float4* clsB = (const float4*)cls + (size_t)b * NA;
    const float*  ctrB = ctr + (size_t)b * NA;

    // ============ P1: zero grank slice + approx-score histogram =============
    if (r == 0 && tid == 0) gcnt[b] = 0;
    if (tid < 512) grank[b][r * 512 + tid] = 0u;
    for (int i = r * NT + tid; i < NA; i += 8 * NT) {
        float4 c = clsB[i];
        float m = fmaxf(fmaxf(c.x, c.y), fmaxf(c.z, c.w));   // sigmoid monotone
        float score = __fsqrt_rn(siga(m) * siga(ctrB[i]));
        atomicAdd(&ghist[b][__float_as_uint(score) >> 16], 1u);
    }
    bbarrier(b, 0);

    // ============ P2: threshold (warp scans) + fused compact/rescore ========
    { unsigned s = 0; int base = tid * 16;
#pragma unroll
      for (int q = 0; q < 16; ++q) s += ghist[b][base + q];
      chunk[tid] = s; }
    __syncthreads();
    { unsigned s = chunk[wid * 32 + lane];
#pragma unroll
      for (int o = 16; o; o >>= 1) s += __shfl_xor_sync(FULL, s, o);
      if (lane == 0) supr[wid] = s; }
    __syncthreads();
    if (wid == 0) {
        unsigned suf = suffix_sum(supr[lane], lane);
        unsigned m1  = __ballot_sync(FULL, suf >= KTOP);
        int sblk     = 31 - __clz(m1);
        unsigned above = (sblk < 31) ? __shfl_sync(FULL, suf, sblk + 1) : 0u;
        unsigned cs  = suffix_sum(chunk[sblk * 32 + lane], lane);
        unsigned m2  = __ballot_sync(FULL, cs + above >= KTOP);
        int cc       = 31 - __clz(m2);
        unsigned above2 = above + ((cc < 31) ? __shfl_sync(FULL, cs, cc + 1) : 0u);
        int binbase  = (sblk * 32 + cc) * 16;
        unsigned bs  = suffix_sum((lane < 16) ? ghist[b][binbase + lane] : 0u, lane);
        unsigned m3  = __ballot_sync(FULL, bs + above2 >= KTOP);
        int bb       = 31 - __clz(m3);
        if (lane == 0) {
            int T = binbase + bb;
            s_thr = (T > 0) ? (unsigned)(T - 1) : 0u;   // one-bin superset margin
        }
    }
    __syncthreads();
    const unsigned T = s_thr;

    for (int i = r * NT + tid; i < NA; i += 8 * NT) {
        float4 c = clsB[i];
        float xs0 = c.x, xs1 = c.y, xs2 = c.z, xs3 = c.w;
        float m = fmaxf(fmaxf(xs0, xs1), fmaxf(xs2, xs3));
        float ctrv = ctrB[i];
        float sa = __fsqrt_rn(siga(m) * siga(ctrv));
        if ((__float_as_uint(sa) >> 16) >= T) {
            unsigned p = atomicAdd(&gcnt[b], 1u);
            if (p < CCAP) {
                int im = 0; float mm = xs0;
                if (xs1 > mm) { mm = xs1; im = 1; }
                if (xs2 > mm) { mm = xs2; im = 2; }
                if (xs3 > mm) { mm = xs3; im = 3; }
                float sm = sigx(mm);                    // == max of the 4 sigmoids
                int lab = im;
                if (im > 0) {                           // first-argmax tie guard
                    float lim = mm - 1e-4f;
                    if (xs0 > lim || (im > 1 && xs1 > lim) || (im > 2 && xs2 > lim)) {
                        if (xs0 > lim && sigx(xs0) == sm) lab = 0;
                        else if (im > 1 && xs1 > lim && sigx(xs1) == sm) lab = 1;
                        else if (im > 2 && xs2 > lim && sigx(xs2) == sm) lab = 2;
                    }
                }
                float sctr  = sigx(ctrv);
                float score = __fsqrt_rn(__fmul_rn(sm, sctr));
                gkey[b][p] = ((u64)__float_as_uint(score) << 32)
                           | ((u64)(0x7FFFu - (unsigned)i) << 4) | (u64)(lab + 1);
            }
        }
    }
    bbarrier(b, 1);

    int C = (int)gcnt[b]; if (C > CCAP) C = CCAP;

    // ============ P3: brute-force rank (8 CTAs, O(C^2)/8 each) ==============
    {
        u64* skeys = (u64*)smem_raw;
        for (int i = tid; i < C; i += NT) skeys[i] = gkey[b][i];
        __syncthreads();
        int j0 = (r * C) >> 3, j1 = ((r + 1) * C) >> 3;
        for (int i = tid; i < C; i += NT) {
            u64 ki = skeys[i];
            unsigned cnt = 0;
#pragma unroll 4
            for (int j = j0; j < j1; ++j) cnt += (skeys[j] > ki) ? 1u : 0u;
            if (cnt) atomicAdd(&grank[b][i], cnt);
        }
    }
    bbarrier(b, 2);

    // ============ P4: r==0 gather-by-rank + boxes; r>0 zero hist/nz =========
    if (r == 0) {
        u64* skey = (u64*)smem_raw;             // KTOP u64
        for (int i = tid; i < C; i += NT) {
            unsigned rk = grank[b][i];
            if (rk < KTOP) skey[rk] = gkey[b][i];
        }
        __syncthreads();

        float x1 = 0, y1 = 0, x2 = 0, y2 = 0, score = 0;
        int label = 0; bool validf = false;
        if (tid < KTOP) {
            u64 key = skey[tid];
            score  = __uint_as_float((unsigned)(key >> 32));
            label  = (int)(key & 0xFull);
            int idx = 0x7FFF - (int)((key >> 4) & 0x7FFFull);
            validf = (score >= 0.05f);

            float4 r4 = ((const float4*)reg)[(size_t)b * NA + idx];
            float2 xy = ((const float2*)coords)[idx];
            float  st = pstr[idx];
            x1 = __fsub_rn(xy.x, __fmul_rn(r4.x, st));
            y1 = __fsub_rn(xy.y, __fmul_rn(r4.y, st));
            x2 = __fadd_rn(xy.x, __fmul_rn(r4.z, st));
            y2 = __fadd_rn(xy.y, __fmul_rn(r4.w, st));
            x1 = fminf(fmaxf(x1, 0.0f), 1023.0f);
            y1 = fminf(fmaxf(y1, 0.0f), 799.0f);
            x2 = fminf(fmaxf(x2, 0.0f), 1023.0f);
            y2 = fminf(fmaxf(y2, 0.0f), 799.0f);

            gsbox[b][tid] = make_float4(x1, y1, x2, y2);
            gssc[b][tid]  = score;
            gslab[b][tid] = (unsigned)label;
        }
        { unsigned vb = __ballot_sync(FULL, validf);
          if (lane == 0) gvbits[b][wid] = vb; }

        float vmax = -1000000000.0f, vmin = 1000000000.0f;
        if (tid < KTOP && validf) {
            vmax = fmaxf(fmaxf(x1, y1), fmaxf(x2, y2));
            vmin = fminf(fminf(x1, y1), fminf(x2, y2));
        }
#pragma unroll
        for (int o = 16; o; o >>= 1) {
            vmax = fmaxf(vmax, __shfl_xor_sync(FULL, vmax, o));
            vmin = fminf(vmin, __shfl_xor_sync(FULL, vmin, o));
        }
        if (lane == 0) { redmax[wid] = vmax; redmin[wid] = vmin; }
        __syncthreads();
        if (tid == 0) {
            float mx = redmax[0], mn = redmin[0];
            for (int w = 1; w < 32; ++w) { mx = fmaxf(mx, redmax[w]); mn = fminf(mn, redmin[w]); }
            s_mx = mx; s_mn = mn;
        }
        __syncthreads();
        if (tid < KTOP) {
            float off = __fmul_rn((float)label, __fadd_rn(__fsub_rn(s_mx, s_mn), 1.0f));
            float a  = __fadd_rn(x1, off), bb = __fadd_rn(y1, off);
            float cc = __fadd_rn(x2, off), dd = __fadd_rn(y2, off);
            gsx1[b][tid] = a;  gsy1[b][tid] = bb;
            gsx2[b][tid] = cc; gsy2[b][tid] = dd;
            gsar[b][tid] = __fmul_rn(__fsub_rn(cc, a), __fsub_rn(dd, bb));
        }
    } else {
        int z0 = (r - 1) * 2341, z1 = (r == 7) ? NBINS : z0 + 2341;
        for (int i = z0 + tid; i < z1; i += NT) ghist[b][i] = 0;
        if (r == 1 && tid < 32) gnzw[b][tid] = 0u;
    }
    bbarrier(b, 3);

    // ============ P5: bit-matrix + diag + nz bitmap (all 8 CTAs) ============
    {
        float* sx1 = (float*)smem_raw;
        float* sy1 = sx1 + KTOP; float* sx2 = sy1 + KTOP;
        float* sy2 = sx2 + KTOP; float* sar = sy2 + KTOP;
        for (int j = tid; j < KTOP; j += NT) {
            sx1[j] = gsx1[b][j]; sy1[j] = gsy1[b][j];
            sx2[j] = gsx2[b][j]; sy2[j] = gsy2[b][j];
            sar[j] = gsar[b][j];
        }
        __syncthreads();

        for (int k = wid; k < 125; k += 32) {
            int i = r + 8 * k;                        // interleaved -> balanced
            float ax1 = sx1[i], ay1 = sy1[i], ax2 = sx2[i], ay2 = sy2[i], aa = sar[i];
            unsigned myword = 0;
            int jc0 = (i + 1) >> 5;
            for (int jc = jc0; jc < 32; ++jc) {       // uniform per warp
                int j = jc * 32 + lane;
                bool sup = false;
                if (j > i && j < KTOP) {
                    float ix1 = fmaxf(ax1, sx1[j]);
                    float iy1 = fmaxf(ay1, sy1[j]);
                    float ix2 = fminf(ax2, sx2[j]);
                    float iy2 = fminf(ay2, sy2[j]);
                    float iw  = fmaxf(__fsub_rn(ix2, ix1), 0.0f);
                    float ih  = fmaxf(__fsub_rn(iy2, iy1), 0.0f);
                    float inter = __fmul_rn(iw, ih);
                    float uni = fmaxf(__fsub_rn(__fadd_rn(aa, sar[j]), inter), 1e-9f);
                    sup = __fdiv_rn(inter, uni) > 0.5f;
                }
                unsigned wbits = __ballot_sync(FULL, sup);
                if (lane == jc) myword = wbits;
            }
            gmat[b][i][lane] = myword;
            if (lane == (i >> 5)) gdiag[b][i] = myword;
            unsigned any = __ballot_sync(FULL, myword != 0u);
            if (lane == 0 && any) atomicOr(&gnzw[b][i >> 5], 1u << (i & 31));
        }
    }
    bbarrier(b, 4);

    // ============ P6: sparse block-serial NMS + outputs (r==0) ==============
    if (r != 0) return;
    {
        unsigned* sdiag = (unsigned*)smem_raw;        // 1024 u32
        sdiag[tid] = (tid < KTOP) ? gdiag[b][tid] : 0u;
        __syncthreads();

        if (wid == 0) {
            unsigned removed = ~gvbits[b][lane];      // lane owns [32l, 32l+32)
            unsigned nz = gnzw[b][lane];              // lane bk -> block bk nz word
            for (int bk = 0; bk < 32; ++bk) {
                unsigned curw = __shfl_sync(FULL, removed, bk);
                unsigned kept = 0;
                if (lane == 0) {
                    const uint4* dg = (const uint4*)(sdiag + bk * 32);
                    uint4 v0 = dg[0], v1 = dg[1], v2 = dg[2], v3 = dg[3];
                    uint4 v4 = dg[4], v5 = dg[5], v6 = dg[6], v7 = dg[7];
                    unsigned anyd = (v0.x|v0.y|v0.z|v0.w)|(v1.x|v1.y|v1.z|v1.w)
                                  | (v2.x|v2.y|v2.z|v2.w)|(v3.x|v3.y|v3.z|v3.w)
                                  | (v4.x|v4.y|v4.z|v4.w)|(v5.x|v5.y|v5.z|v5.w)
                                  | (v6.x|v6.y|v6.z|v6.w)|(v7.x|v7.y|v7.z|v7.w);
                    if (anyd == 0u) {
                        kept = ~curw;                 // nobody suppresses in-block
                    } else {
                        unsigned rem = curw;
                        const uint4 vv[8] = {v0,v1,v2,v3,v4,v5,v6,v7};
#pragma unroll
                        for (int q = 0; q < 8; ++q) {
                            int j0 = q * 4;
                            if (!((rem >> (j0+0)) & 1u)) { kept |= 1u << (j0+0); rem |= vv[q].x; }
                            if (!((rem >> (j0+1)) & 1u)) { kept |= 1u << (j0+1); rem |= vv[q].y; }
                            if (!((rem >> (j0+2)) & 1u)) { kept |= 1u << (j0+2); rem |= vv[q].z; }
                            if (!((rem >> (j0+3)) & 1u)) { kept |= 1u << (j0+3); rem |= vv[q].w; }
                        }
                    }
                }
                kept = __shfl_sync(FULL, kept, 0);
                unsigned todo = kept & __shfl_sync(FULL, nz, bk);
                while (todo) {                        // warp-uniform
                    int j = __ffs(todo) - 1; todo &= todo - 1;
                    removed |= gmat[b][bk * 32 + j][lane];
                }
            }
            srem[lane] = removed;
        }
        __syncthreads();

        if (tid < KTOP) {
            bool k = ((srem[tid >> 5] >> (tid & 31)) & 1u) == 0u;
            float so = k ? gssc[b][tid] : 0.0f;
            float lo = k ? (float)gslab[b][tid] : 0.0f;
            float4 bx = gsbox[b][tid];
            if (!k) bx = make_float4(0.f, 0.f, 0.f, 0.f);
            out[(size_t)b * KTOP + tid] = so;
            out[(size_t)(B * KTOP) + (size_t)b * KTOP + tid] = lo;
            size_t base = (size_t)(2 * B * KTOP) + ((size_t)b * KTOP + tid) * 4;
            out[base + 0] = bx.x; out[base + 1] = bx.y;
            out[base + 2] = bx.z; out[base + 3] = bx.w;
        }
    }
}

extern "C" void kernel_launch(void* const* d_in, const int* in_sizes, int n_in,
                              void* d_out, int out_size) {
    (void)in_sizes; (void)n_in; (void)out_size;
    static bool attr_done = false;
    if (!attr_done) {
        cudaFuncSetAttribute(fcos_persist, cudaFuncAttributeMaxDynamicSharedMemorySize,
                             SMEM_TOTAL);
        attr_done = true;
    }
    fcos_persist<<<NCTA, NT, SMEM_TOTAL>>>(
        (const float*)d_in[0], (const float*)d_in[1], (const float*)d_in[2],
        (const float*)d_in[3], (const float*)d_in[4], (float*)d_out);
}